// round 3
// baseline (speedup 1.0000x reference)
#include <cuda_runtime.h>
#include <math.h>

#define B 2
#define NF 20000
#define NS 30000
#define C 128
#define NKEY 500
#define NROWS (B*NF)

// output layout (flattened, float32, in reference return order)
#define OUT_OFF  0        // (1000,128)
#define KVI_OFF  128000   // (1000,3)
#define HEAT_OFF 131000   // (40000,)
#define S10_OFF  171000   // (40000,10)
#define KC_OFF   571000   // (1000,)

// ---------------- scratch (device globals; no allocs allowed) ----------------
__device__ float g_sig[NROWS];
__device__ int   g_cls[NROWS];
__device__ int   g_topk[B*NKEY];
__device__ float2 g_keyworld[B*NKEY];
__device__ float2 g_srcworld[2][B][NS];
__device__ float g_mf0[B*NKEY*C];
__device__ float g_mf1[B*NKEY*C];

__device__ __forceinline__ float worldc(int c, float stride) {
    // ((c + 0.5) * stride) * 0.075 + (-54), each op fp32-rounded, no contraction
    float t = __fadd_rn((float)c, 0.5f);
    t = __fmul_rn(t, stride);
    t = __fmul_rn(t, 0.075f);
    return __fadd_rn(t, -54.0f);
}

// ---------------- K3: src world coords ----------------
__global__ void srcworld_kernel(const int* __restrict__ ca, const int* __restrict__ cb) {
    int id = blockIdx.x * 256 + threadIdx.x;
    if (id >= 2 * B * NS) return;
    int src = id / (B * NS);
    int rem = id - src * (B * NS);
    int b = rem / NS, i = rem - b * NS;
    int2 cc = ((const int2*)(src == 0 ? ca : cb))[b * NS + i];
    float stride = (src == 0) ? 4.0f : 8.0f;
    g_srcworld[src][b][i] = make_float2(worldc(cc.x, stride), worldc(cc.y, stride));
}

// ---------------- K1: heat MLP (40000 x 128 -> 128 relu -> 10) ----------------
#define SXS 132   // padded row stride for shared X/H (bank-conflict free)
#define HEAT_SMEM ((64*SXS + 128*128 + 128*12 + 64*10) * 4)

__global__ void __launch_bounds__(256) heat_kernel(
    const float* __restrict__ X, const float* __restrict__ W1,
    const float* __restrict__ G1, const float* __restrict__ B1,
    const float* __restrict__ W2, const float* __restrict__ B2v,
    float* __restrict__ outF)
{
    extern __shared__ float sm[];
    float* sX  = sm;                     // 64 * SXS
    float* sW1 = sm + 64 * SXS;          // 128 * 128
    float* sW2 = sW1 + 128 * 128;        // 128 * 12 (padded, cols>=10 zero)
    float* sS  = sW2 + 128 * 12;         // 64 * 10
    const int tid = threadIdx.x;
    const int rowbase = blockIdx.x * 64;

    // load X tile (64x128) into padded shared
    {
        const float4* s = (const float4*)(X + (size_t)rowbase * C);
        #pragma unroll
        for (int t = 0; t < 8; ++t) {
            int idx = tid + t * 256;         // 0..2047 float4s
            int row = idx >> 5, c4 = idx & 31;
            *(float4*)(sX + row * SXS + c4 * 4) = s[idx];
        }
    }
    // load W1 (128x128)
    {
        float4* d = (float4*)sW1;
        const float4* s = (const float4*)W1;
        #pragma unroll
        for (int t = 0; t < 16; ++t) d[tid + t * 256] = s[tid + t * 256];
    }
    // load W2 padded to 12 cols
    for (int t = tid; t < 128 * 12; t += 256) {
        int i = t / 12, c = t - i * 12;
        sW2[t] = (c < 10) ? W2[i * 10 + c] : 0.f;
    }
    __syncthreads();

    const int ty = tid >> 4, tx = tid & 15;
    const int c0 = tx * 8;
    float acc[4][8];
    #pragma unroll
    for (int i = 0; i < 4; ++i)
        #pragma unroll
        for (int j = 0; j < 8; ++j) acc[i][j] = 0.f;

    #pragma unroll 4
    for (int k = 0; k < 128; ++k) {
        float xv[4];
        #pragma unroll
        for (int i = 0; i < 4; ++i) xv[i] = sX[(ty * 4 + i) * SXS + k];
        float4 wa = *(const float4*)&sW1[k * 128 + c0];
        float4 wb = *(const float4*)&sW1[k * 128 + c0 + 4];
        float wv[8] = {wa.x, wa.y, wa.z, wa.w, wb.x, wb.y, wb.z, wb.w};
        #pragma unroll
        for (int i = 0; i < 4; ++i)
            #pragma unroll
            for (int j = 0; j < 8; ++j) acc[i][j] += xv[i] * wv[j];
    }
    float4 ga = *(const float4*)&G1[c0], gb = *(const float4*)&G1[c0 + 4];
    float4 ba = *(const float4*)&B1[c0], bb = *(const float4*)&B1[c0 + 4];
    float gv[8] = {ga.x, ga.y, ga.z, ga.w, gb.x, gb.y, gb.z, gb.w};
    float bv[8] = {ba.x, ba.y, ba.z, ba.w, bb.x, bb.y, bb.z, bb.w};
    __syncthreads();  // all reads of sX done; safe to overwrite with H
    #pragma unroll
    for (int i = 0; i < 4; ++i)
        #pragma unroll
        for (int j = 0; j < 8; ++j) {
            float h = acc[i][j] * gv[j] + bv[j];
            sX[(ty * 4 + i) * SXS + c0 + j] = h > 0.f ? h : 0.f;
        }
    __syncthreads();

    // stage 2: scores10 = H @ W2 + b2
    {
        const int r = tid >> 2, cg = tid & 3;
        const int cc0 = cg * 3;
        float a0 = 0.f, a1 = 0.f, a2 = 0.f;
        for (int i = 0; i < 128; ++i) {
            float hv = sX[r * SXS + i];
            a0 += hv * sW2[i * 12 + cc0];
            a1 += hv * sW2[i * 12 + cc0 + 1];
            a2 += hv * sW2[i * 12 + cc0 + 2];
        }
        float accs[3] = {a0, a1, a2};
        #pragma unroll
        for (int q = 0; q < 3; ++q) {
            int c = cc0 + q;
            if (c < 10) {
                float v = accs[q] + B2v[c];
                outF[S10_OFF + (size_t)(rowbase + r) * 10 + c] = v;
                sS[r * 10 + c] = v;
            }
        }
    }
    __syncthreads();
    if (tid < 64) {
        int r = tid, row = rowbase + r;
        float m = -INFINITY; int a = 0;
        #pragma unroll
        for (int c = 0; c < 10; ++c) {
            float v = sS[r * 10 + c];
            if (v > m) { m = v; a = c; }   // first max wins (jnp.argmax)
        }
        outF[HEAT_OFF + row] = m;
        g_sig[row] = 1.f / (1.f + expf(-m));
        g_cls[row] = a;
    }
}

// ---------------- K2: per-batch top-500 (jax.lax.top_k semantics) ----------------
#define TOPK_SMEM (NF * 4 + 1024 * 8)

__global__ void __launch_bounds__(1024) topk_kernel(
    const int* __restrict__ fusion_coords, float* __restrict__ outF)
{
    extern __shared__ unsigned char dsm[];
    unsigned* sbits = (unsigned*)dsm;                                        // 20000
    unsigned long long* cand = (unsigned long long*)(dsm + NF * sizeof(unsigned)); // 1024
    __shared__ unsigned s_lo, s_hi;
    __shared__ int s_cnt, s_n;
    const int tid = threadIdx.x;
    const int b = blockIdx.x;

    for (int i = tid; i < NF; i += 1024) sbits[i] = __float_as_uint(g_sig[b * NF + i]);
    if (tid == 0) { s_lo = 0u; s_hi = 0x3F800000u; }
    __syncthreads();

    // binary search: max t with count(bits >= t) >= 500
    for (int it = 0; it < 31; ++it) {
        unsigned lo = s_lo, hi = s_hi;
        unsigned mid = lo + ((hi - lo) >> 1);
        if (tid == 0) s_cnt = 0;
        __syncthreads();
        int c = 0;
        for (int i = tid; i < NF; i += 1024) c += (sbits[i] >= mid) ? 1 : 0;
        #pragma unroll
        for (int o = 16; o; o >>= 1) c += __shfl_xor_sync(0xffffffffu, c, o);
        if ((tid & 31) == 0) atomicAdd(&s_cnt, c);
        __syncthreads();
        if (tid == 0) { if (s_cnt >= NKEY) s_lo = mid; else s_hi = mid; }
        __syncthreads();
    }
    unsigned thr = s_lo;
    if (tid == 0) s_n = 0;
    __syncthreads();
    for (int i = tid; i < NF; i += 1024) {
        unsigned v = sbits[i];
        if (v >= thr) {
            int p = atomicAdd(&s_n, 1);
            if (p < 1024)
                cand[p] = ((unsigned long long)v << 32) |
                          (unsigned long long)(0xFFFFFFFFu - (unsigned)i);
        }
    }
    __syncthreads();
    int n = s_n; if (n > 1024) n = 1024;
    if (tid >= n) cand[tid] = 0ull;
    __syncthreads();
    // bitonic sort ascending, 1024 elems
    for (int k = 2; k <= 1024; k <<= 1) {
        for (int j = k >> 1; j > 0; j >>= 1) {
            int ixj = tid ^ j;
            if (ixj > tid) {
                unsigned long long a = cand[tid], d = cand[ixj];
                bool up = ((tid & k) == 0);
                if ((a > d) == up) { cand[tid] = d; cand[ixj] = a; }
            }
            __syncthreads();
        }
    }
    if (tid < NKEY) {
        unsigned long long key = cand[1023 - tid];
        unsigned idx = 0xFFFFFFFFu - (unsigned)(key & 0xFFFFFFFFull);
        g_topk[b * NKEY + tid] = (int)idx;
        int2 cc = ((const int2*)fusion_coords)[b * NF + (int)idx];
        int o = (b * NKEY + tid) * 3;
        outF[KVI_OFF + o + 0] = (float)b;
        outF[KVI_OFF + o + 1] = (float)cc.x;
        outF[KVI_OFF + o + 2] = (float)cc.y;
        g_keyworld[b * NKEY + tid] = make_float2(worldc(cc.x, 8.0f), worldc(cc.y, 8.0f));
        outF[KC_OFF + b * NKEY + tid] = (float)g_cls[b * NF + (int)idx];
    }
}

// ---------------- K4: radius-KNN top-16 + neighbor-weight reduction ----------------
#define KNN_CHUNK 5000

__global__ void __launch_bounds__(512) knn_kernel(
    const float* __restrict__ fa, const float* __restrict__ fb,
    const float* __restrict__ knn_w, const float* __restrict__ knn_b)
{
    __shared__ float2 schunk[KNN_CHUNK];
    __shared__ unsigned long long sel[16][16];
    const int b = blockIdx.y, src = blockIdx.z;
    const int warpId = threadIdx.x >> 5, lane = threadIdx.x & 31;
    const int key = blockIdx.x * 16 + warpId;
    const bool active = key < NKEY;
    float kx = 0.f, ky = 0.f;
    if (active) { float2 kw = g_keyworld[b * NKEY + key]; kx = kw.x; ky = kw.y; }
    // radius^2 computed in double by python then compared in f32 by jnp
    const float r2 = (src == 0) ? 5.76f : 23.04f;
    unsigned long long lst[16];
    #pragma unroll
    for (int q = 0; q < 16; ++q) lst[q] = 0xFFFFFFFFFFFFFFFFull;

    for (int c0 = 0; c0 < NS; c0 += KNN_CHUNK) {
        for (int i = threadIdx.x; i < KNN_CHUNK; i += 512)
            schunk[i] = g_srcworld[src][b][c0 + i];
        __syncthreads();
        if (active) {
            for (int i = lane; i < KNN_CHUNK; i += 32) {
                float2 s = schunk[i];
                float dx = kx - s.x;
                float dy = ky - s.y;
                float d2 = __fadd_rn(__fmul_rn(dx, dx), __fmul_rn(dy, dy));
                if (d2 <= r2) {
                    unsigned long long kk =
                        ((unsigned long long)__float_as_uint(d2) << 32) |
                        (unsigned long long)(unsigned)(c0 + i);
                    if (kk < lst[15]) {
                        unsigned long long cur = kk;
                        #pragma unroll
                        for (int q = 0; q < 16; ++q) {
                            unsigned long long mn = lst[q] < cur ? lst[q] : cur;
                            cur = lst[q] < cur ? cur : lst[q];
                            lst[q] = mn;
                        }
                    }
                }
            }
        }
        __syncthreads();
    }

    if (active) {
        // warp merge: global lexicographic-min extraction, 16 rounds
        int hp = 0;
        for (int r = 0; r < 16; ++r) {
            unsigned long long mine = (hp < 16) ? lst[hp] : 0xFFFFFFFFFFFFFFFFull;
            unsigned long long best = mine;
            #pragma unroll
            for (int o = 16; o; o >>= 1) {
                unsigned long long other = __shfl_xor_sync(0xffffffffu, best, o);
                best = other < best ? other : best;
            }
            unsigned msk = __ballot_sync(0xffffffffu, mine == best);
            if (lane == __ffs((int)msk) - 1) hp++;
            if (lane == 0) sel[warpId][r] = best;
        }
        __syncwarp();
        const float* feat = ((src == 0) ? fa : fb) + (size_t)b * NS * C;
        float4 acc = make_float4(0.f, 0.f, 0.f, 0.f);
        for (int r = 0; r < 16; ++r) {
            unsigned long long kk = sel[warpId][r];
            if (kk != 0xFFFFFFFFFFFFFFFFull) {
                unsigned idx = (unsigned)(kk & 0xFFFFFFFFull);
                float4 v = *(const float4*)(feat + (size_t)idx * C + lane * 4);
                float w = knn_w[src * 16 + r];
                acc.x += w * v.x; acc.y += w * v.y; acc.z += w * v.z; acc.w += w * v.w;
            }
        }
        float bb = knn_b[src];
        float* dst = (src == 0 ? g_mf0 : g_mf1) + (size_t)(b * NKEY + key) * C + lane * 4;
        dst[0] = acc.x + bb; dst[1] = acc.y + bb; dst[2] = acc.z + bb; dst[3] = acc.w + bb;
    }
}

// ---------------- K5: kw MLP + softmax fusion + fuse MLP ----------------
__global__ void __launch_bounds__(256) fuse_kernel(
    const float* __restrict__ fusion_feat,
    const float* __restrict__ kw1, const float* __restrict__ kg1,
    const float* __restrict__ kb1, const float* __restrict__ kw2,
    const float* __restrict__ kb2,
    const float* __restrict__ fw1, const float* __restrict__ fg1,
    const float* __restrict__ fb1, const float* __restrict__ fw2,
    const float* __restrict__ fb2, float* __restrict__ outF)
{
    __shared__ float kf[8][128];
    __shared__ float h64[8][64];
    __shared__ float logit[8][3];
    __shared__ float sw[8][3];
    __shared__ float fused[8][256];
    __shared__ float h256[8][256];
    const int tid = threadIdx.x;
    const int g0 = blockIdx.x * 8;

    for (int t = tid; t < 8 * 128; t += 256) {
        int k = t >> 7, c = t & 127;
        int g = g0 + k;
        int b = g / NKEY;
        int ki = g_topk[g];
        kf[k][c] = fusion_feat[((size_t)b * NF + ki) * C + c];
    }
    __syncthreads();
    for (int t = tid; t < 512; t += 256) {
        int k = t >> 6, j = t & 63;
        float a = 0.f;
        for (int i = 0; i < 128; ++i) a += kf[k][i] * kw1[i * 64 + j];
        a = a * kg1[j] + kb1[j];
        h64[k][j] = a > 0.f ? a : 0.f;
    }
    __syncthreads();
    if (tid < 24) {
        int k = tid / 3, j = tid - k * 3;
        float a = 0.f;
        for (int i = 0; i < 64; ++i) a += h64[k][i] * kw2[i * 3 + j];
        logit[k][j] = a + kb2[j];
    }
    __syncthreads();
    if (tid < 8) {
        float l0 = logit[tid][0], l1 = logit[tid][1], l2 = logit[tid][2];
        float m = fmaxf(l0, fmaxf(l1, l2));
        float e0 = expf(l0 - m), e1 = expf(l1 - m), e2 = expf(l2 - m);
        float s = e0 + e1 + e2;
        sw[tid][0] = e0 / s; sw[tid][1] = e1 / s; sw[tid][2] = e2 / s;
    }
    __syncthreads();
    for (int t = tid; t < 1024; t += 256) {
        int k = t >> 7, c = t & 127;
        int g = g0 + k;
        float x = kf[k][c];
        float kv = sw[k][0] * x;
        float fs = kv * g_mf0[(size_t)g * C + c];
        kv = sw[k][1] * kv;
        fs += kv * g_mf1[(size_t)g * C + c];
        fused[k][c] = fs;
        fused[k][128 + c] = kv;
    }
    __syncthreads();
    {
        float acc[8];
        #pragma unroll
        for (int k = 0; k < 8; ++k) acc[k] = 0.f;
        for (int i = 0; i < 256; ++i) {
            float wv = fw1[i * 256 + tid];
            #pragma unroll
            for (int k = 0; k < 8; ++k) acc[k] += fused[k][i] * wv;
        }
        float gg = fg1[tid], bb = fb1[tid];
        #pragma unroll
        for (int k = 0; k < 8; ++k) {
            float h = acc[k] * gg + bb;
            h256[k][tid] = h > 0.f ? h : 0.f;
        }
    }
    __syncthreads();
    for (int t = tid; t < 1024; t += 256) {
        int k = t >> 7, c = t & 127;
        int g = g0 + k;
        float a = 0.f;
        for (int i = 0; i < 256; ++i) a += h256[k][i] * fw2[i * 128 + c];
        outF[OUT_OFF + (size_t)g * 128 + c] = a + fb2[c];
    }
}

// ---------------- launch ----------------
extern "C" void kernel_launch(void* const* d_in, const int* in_sizes, int n_in,
                              void* d_out, int out_size)
{
    const float* fusion_feat = (const float*)d_in[0];
    const float* src_feat_a  = (const float*)d_in[1];
    const float* src_feat_b  = (const float*)d_in[2];
    const float* heat_w1 = (const float*)d_in[3];
    const float* heat_g1 = (const float*)d_in[4];
    const float* heat_b1 = (const float*)d_in[5];
    const float* heat_w2 = (const float*)d_in[6];
    const float* heat_b2 = (const float*)d_in[7];
    const float* knn_w = (const float*)d_in[8];
    const float* knn_b = (const float*)d_in[9];
    const float* kw_w1 = (const float*)d_in[10];
    const float* kw_g1 = (const float*)d_in[11];
    const float* kw_b1 = (const float*)d_in[12];
    const float* kw_w2 = (const float*)d_in[13];
    const float* kw_b2 = (const float*)d_in[14];
    const float* fuse_w1 = (const float*)d_in[15];
    const float* fuse_g1 = (const float*)d_in[16];
    const float* fuse_b1 = (const float*)d_in[17];
    const float* fuse_w2 = (const float*)d_in[18];
    const float* fuse_b2 = (const float*)d_in[19];
    const int* fusion_coords = (const int*)d_in[20];
    const int* src_coords_a  = (const int*)d_in[21];
    const int* src_coords_b  = (const int*)d_in[22];
    float* outF = (float*)d_out;

    cudaFuncSetAttribute(heat_kernel, cudaFuncAttributeMaxDynamicSharedMemorySize, HEAT_SMEM);
    cudaFuncSetAttribute(topk_kernel, cudaFuncAttributeMaxDynamicSharedMemorySize, TOPK_SMEM);

    srcworld_kernel<<<(2 * B * NS + 255) / 256, 256>>>(src_coords_a, src_coords_b);
    heat_kernel<<<NROWS / 64, 256, HEAT_SMEM>>>(fusion_feat, heat_w1, heat_g1,
                                                heat_b1, heat_w2, heat_b2, outF);
    topk_kernel<<<B, 1024, TOPK_SMEM>>>(fusion_coords, outF);
    dim3 kg(32, B, 2);
    knn_kernel<<<kg, 512>>>(src_feat_a, src_feat_b, knn_w, knn_b);
    fuse_kernel<<<(B * NKEY) / 8, 256>>>(fusion_feat, kw_w1, kw_g1, kw_b1, kw_w2,
                                         kw_b2, fuse_w1, fuse_g1, fuse_b1,
                                         fuse_w2, fuse_b2, outF);
}

// round 4
// speedup vs baseline: 1.5208x; 1.5208x over previous
#include <cuda_runtime.h>
#include <math.h>

#define B 2
#define NF 20000
#define NS 30000
#define C 128
#define NKEY 500
#define NROWS (B*NF)

// output layout (flattened, float32, in reference return order)
#define OUT_OFF  0        // (1000,128)
#define KVI_OFF  128000   // (1000,3)
#define HEAT_OFF 131000   // (40000,)
#define S10_OFF  171000   // (40000,10)
#define KC_OFF   571000   // (1000,)

// spatial binning params (cell > radius with wide margin -> 3x3 ring suffices)
#define DIM0 36
#define CELL0 3.0f
#define NCELL0 (DIM0*DIM0)
#define DIM1 22
#define CELL1 5.0f
#define NCELL1 (DIM1*DIM1)
#define NCELLMAX NCELL0

// ---------------- scratch (device globals; no allocs allowed) ----------------
__device__ float g_sig[NROWS];
__device__ int   g_cls[NROWS];
__device__ int   g_topk[B*NKEY];
__device__ float2 g_keyworld[B*NKEY];
__device__ float2 g_srcworld[2][B][NS];
__device__ float g_mf0[B*NKEY*C];
__device__ float g_mf1[B*NKEY*C];
__device__ int   g_cellcnt[2][B][NCELLMAX];
__device__ int   g_cellstart[2][B][NCELLMAX+1];
__device__ int   g_cellfill[2][B][NCELLMAX];
__device__ int   g_ptcell[2][B][NS];
__device__ float2 g_sortedWorld[2][B][NS];
__device__ int    g_sortedIdx[2][B][NS];

__device__ __forceinline__ float worldc(int c, float stride) {
    // ((c + 0.5) * stride) * 0.075 + (-54), each op fp32-rounded, no contraction
    float t = __fadd_rn((float)c, 0.5f);
    t = __fmul_rn(t, stride);
    t = __fmul_rn(t, 0.075f);
    return __fadd_rn(t, -54.0f);
}

// ---------------- bin build ----------------
__global__ void bin_zero_kernel() {
    for (int i = threadIdx.x; i < 2 * B * NCELLMAX; i += 1024)
        ((int*)g_cellcnt)[i] = 0;
}

__global__ void bin_hist_kernel(const int* __restrict__ ca, const int* __restrict__ cb) {
    int id = blockIdx.x * 256 + threadIdx.x;
    if (id >= 2 * B * NS) return;
    int src = id / (B * NS);
    int rem = id - src * (B * NS);
    int b = rem / NS, i = rem - b * NS;
    int2 cc = ((const int2*)(src == 0 ? ca : cb))[b * NS + i];
    float stride = (src == 0) ? 4.0f : 8.0f;
    float wx = worldc(cc.x, stride), wy = worldc(cc.y, stride);
    g_srcworld[src][b][i] = make_float2(wx, wy);
    float cell = (src == 0) ? CELL0 : CELL1;
    int dim = (src == 0) ? DIM0 : DIM1;
    int cx = (int)floorf((wx + 54.0f) / cell);
    int cy = (int)floorf((wy + 54.0f) / cell);
    cx = min(dim - 1, max(0, cx));
    cy = min(dim - 1, max(0, cy));
    int cid = cy * dim + cx;
    g_ptcell[src][b][i] = cid;
    atomicAdd(&g_cellcnt[src][b][cid], 1);
}

__global__ void __launch_bounds__(1024) bin_prefix_kernel() {
    int src = blockIdx.x >> 1, b = blockIdx.x & 1;
    int n = (src == 0) ? NCELL0 : NCELL1;
    const int* cnt = g_cellcnt[src][b];
    int* start = g_cellstart[src][b];
    int* fill = g_cellfill[src][b];
    __shared__ int warpsum[32];
    int tid = threadIdx.x, lane = tid & 31, wid = tid >> 5;
    int e0 = (2 * tid < n) ? cnt[2 * tid] : 0;
    int e1 = (2 * tid + 1 < n) ? cnt[2 * tid + 1] : 0;
    int s = e0 + e1;
    int v = s;
    #pragma unroll
    for (int o = 1; o < 32; o <<= 1) {
        int t = __shfl_up_sync(0xffffffffu, v, o);
        if (lane >= o) v += t;
    }
    if (lane == 31) warpsum[wid] = v;
    __syncthreads();
    if (wid == 0) {
        int w = warpsum[lane];
        #pragma unroll
        for (int o = 1; o < 32; o <<= 1) {
            int t = __shfl_up_sync(0xffffffffu, w, o);
            if (lane >= o) w += t;
        }
        warpsum[lane] = w;
    }
    __syncthreads();
    int base = ((wid > 0) ? warpsum[wid - 1] : 0) + (v - s);
    if (2 * tid < n)     { start[2 * tid] = base;          fill[2 * tid] = base; }
    if (2 * tid + 1 < n) { start[2 * tid + 1] = base + e0; fill[2 * tid + 1] = base + e0; }
    if (tid == 0) start[n] = warpsum[31];
}

__global__ void bin_scatter_kernel() {
    int id = blockIdx.x * 256 + threadIdx.x;
    if (id >= 2 * B * NS) return;
    int src = id / (B * NS);
    int rem = id - src * (B * NS);
    int b = rem / NS, i = rem - b * NS;
    int cid = g_ptcell[src][b][i];
    int pos = atomicAdd(&g_cellfill[src][b][cid], 1);
    g_sortedWorld[src][b][pos] = g_srcworld[src][b][i];
    g_sortedIdx[src][b][pos] = i;
}

// ---------------- K1: heat MLP (40000 x 128 -> 128 relu -> 10) ----------------
#define SXS 132   // padded row stride for shared X/H
#define HEAT_SMEM ((64*SXS + 128*128 + 128*12 + 64*10) * 4)

__global__ void __launch_bounds__(128) heat_kernel(
    const float* __restrict__ X, const float* __restrict__ W1,
    const float* __restrict__ G1, const float* __restrict__ B1,
    const float* __restrict__ W2, const float* __restrict__ B2v,
    float* __restrict__ outF)
{
    extern __shared__ float sm[];
    float* sX  = sm;                     // 64 * SXS
    float* sW1 = sm + 64 * SXS;          // 128 * 128
    float* sW2 = sW1 + 128 * 128;        // 128 * 12 (padded, cols>=10 zero)
    float* sS  = sW2 + 128 * 12;         // 64 * 10
    const int tid = threadIdx.x;
    const int rowbase = blockIdx.x * 64;

    // load X tile (64x128) into padded shared
    {
        const float4* s = (const float4*)(X + (size_t)rowbase * C);
        #pragma unroll
        for (int t = 0; t < 16; ++t) {
            int idx = tid + t * 128;         // 0..2047 float4s
            int row = idx >> 5, c4 = idx & 31;
            *(float4*)(sX + row * SXS + c4 * 4) = s[idx];
        }
    }
    // load W1 (128x128)
    {
        float4* d = (float4*)sW1;
        const float4* s = (const float4*)W1;
        #pragma unroll
        for (int t = 0; t < 32; ++t) d[tid + t * 128] = s[tid + t * 128];
    }
    // load W2 padded to 12 cols
    for (int t = tid; t < 128 * 12; t += 128) {
        int i = t / 12, c = t - i * 12;
        sW2[t] = (c < 10) ? W2[i * 10 + c] : 0.f;
    }
    __syncthreads();

    // 8 thread-rows x 16 thread-cols; 8x8 micro-tile per thread
    const int ty = tid >> 4, tx = tid & 15;
    const int r0 = ty * 8, c0 = tx * 8;
    float acc[8][8];
    #pragma unroll
    for (int i = 0; i < 8; ++i)
        #pragma unroll
        for (int j = 0; j < 8; ++j) acc[i][j] = 0.f;

    for (int k = 0; k < 128; k += 4) {
        float4 xr[8];
        #pragma unroll
        for (int i = 0; i < 8; ++i)
            xr[i] = *(const float4*)&sX[(r0 + i) * SXS + k];
        #pragma unroll
        for (int kk = 0; kk < 4; ++kk) {
            float4 wa = *(const float4*)&sW1[(k + kk) * 128 + c0];
            float4 wb = *(const float4*)&sW1[(k + kk) * 128 + c0 + 4];
            #pragma unroll
            for (int i = 0; i < 8; ++i) {
                float x = (kk == 0) ? xr[i].x : (kk == 1) ? xr[i].y
                        : (kk == 2) ? xr[i].z : xr[i].w;
                acc[i][0] += x * wa.x; acc[i][1] += x * wa.y;
                acc[i][2] += x * wa.z; acc[i][3] += x * wa.w;
                acc[i][4] += x * wb.x; acc[i][5] += x * wb.y;
                acc[i][6] += x * wb.z; acc[i][7] += x * wb.w;
            }
        }
    }
    float4 ga = *(const float4*)&G1[c0], gb = *(const float4*)&G1[c0 + 4];
    float4 ba = *(const float4*)&B1[c0], bb = *(const float4*)&B1[c0 + 4];
    float gv[8] = {ga.x, ga.y, ga.z, ga.w, gb.x, gb.y, gb.z, gb.w};
    float bv[8] = {ba.x, ba.y, ba.z, ba.w, bb.x, bb.y, bb.z, bb.w};
    __syncthreads();  // all reads of sX done; safe to overwrite with H
    #pragma unroll
    for (int i = 0; i < 8; ++i)
        #pragma unroll
        for (int j = 0; j < 8; ++j) {
            float h = acc[i][j] * gv[j] + bv[j];
            sX[(r0 + i) * SXS + c0 + j] = h > 0.f ? h : 0.f;
        }
    __syncthreads();

    // stage 2: scores10 = H @ W2 + b2  (2 threads per row, 5 cols each)
    {
        const int r = tid >> 1, hhalf = tid & 1;
        const int cc0 = hhalf * 5;
        float a[5] = {0.f, 0.f, 0.f, 0.f, 0.f};
        for (int i = 0; i < 128; ++i) {
            float hv = sX[r * SXS + i];
            #pragma unroll
            for (int q = 0; q < 5; ++q) a[q] += hv * sW2[i * 12 + cc0 + q];
        }
        #pragma unroll
        for (int q = 0; q < 5; ++q) {
            int c = cc0 + q;
            float v = a[q] + B2v[c];
            outF[S10_OFF + (size_t)(rowbase + r) * 10 + c] = v;
            sS[r * 10 + c] = v;
        }
    }
    __syncthreads();
    if (tid < 64) {
        int r = tid, row = rowbase + r;
        float m = -INFINITY; int a = 0;
        #pragma unroll
        for (int c = 0; c < 10; ++c) {
            float v = sS[r * 10 + c];
            if (v > m) { m = v; a = c; }   // first max wins (jnp.argmax)
        }
        outF[HEAT_OFF + row] = m;
        g_sig[row] = 1.f / (1.f + expf(-m));
        g_cls[row] = a;
    }
}

// ---------------- K2: per-batch top-500 (jax.lax.top_k semantics) ----------------
#define TOPK_SMEM (NF * 4 + 1024 * 8)

__global__ void __launch_bounds__(1024) topk_kernel(
    const int* __restrict__ fusion_coords, float* __restrict__ outF)
{
    extern __shared__ unsigned char dsm[];
    unsigned* sbits = (unsigned*)dsm;                                        // 20000
    unsigned long long* cand = (unsigned long long*)(dsm + NF * sizeof(unsigned)); // 1024
    __shared__ unsigned s_lo, s_hi;
    __shared__ int s_cnt, s_n;
    const int tid = threadIdx.x;
    const int b = blockIdx.x;

    for (int i = tid; i < NF; i += 1024) sbits[i] = __float_as_uint(g_sig[b * NF + i]);
    if (tid == 0) { s_lo = 0u; s_hi = 0x3F800000u; }
    __syncthreads();

    // binary search: max t with count(bits >= t) >= 500
    for (int it = 0; it < 31; ++it) {
        unsigned lo = s_lo, hi = s_hi;
        unsigned mid = lo + ((hi - lo) >> 1);
        if (tid == 0) s_cnt = 0;
        __syncthreads();
        int c = 0;
        for (int i = tid; i < NF; i += 1024) c += (sbits[i] >= mid) ? 1 : 0;
        #pragma unroll
        for (int o = 16; o; o >>= 1) c += __shfl_xor_sync(0xffffffffu, c, o);
        if ((tid & 31) == 0) atomicAdd(&s_cnt, c);
        __syncthreads();
        if (tid == 0) { if (s_cnt >= NKEY) s_lo = mid; else s_hi = mid; }
        __syncthreads();
    }
    unsigned thr = s_lo;
    if (tid == 0) s_n = 0;
    __syncthreads();
    for (int i = tid; i < NF; i += 1024) {
        unsigned v = sbits[i];
        if (v >= thr) {
            int p = atomicAdd(&s_n, 1);
            if (p < 1024)
                cand[p] = ((unsigned long long)v << 32) |
                          (unsigned long long)(0xFFFFFFFFu - (unsigned)i);
        }
    }
    __syncthreads();
    int n = s_n; if (n > 1024) n = 1024;
    if (tid >= n) cand[tid] = 0ull;
    __syncthreads();
    // bitonic sort ascending, 1024 elems
    for (int k = 2; k <= 1024; k <<= 1) {
        for (int j = k >> 1; j > 0; j >>= 1) {
            int ixj = tid ^ j;
            if (ixj > tid) {
                unsigned long long a = cand[tid], d = cand[ixj];
                bool up = ((tid & k) == 0);
                if ((a > d) == up) { cand[tid] = d; cand[ixj] = a; }
            }
            __syncthreads();
        }
    }
    if (tid < NKEY) {
        unsigned long long key = cand[1023 - tid];
        unsigned idx = 0xFFFFFFFFu - (unsigned)(key & 0xFFFFFFFFull);
        g_topk[b * NKEY + tid] = (int)idx;
        int2 cc = ((const int2*)fusion_coords)[b * NF + (int)idx];
        int o = (b * NKEY + tid) * 3;
        outF[KVI_OFF + o + 0] = (float)b;
        outF[KVI_OFF + o + 1] = (float)cc.x;
        outF[KVI_OFF + o + 2] = (float)cc.y;
        g_keyworld[b * NKEY + tid] = make_float2(worldc(cc.x, 8.0f), worldc(cc.y, 8.0f));
        outF[KC_OFF + b * NKEY + tid] = (float)g_cls[b * NF + (int)idx];
    }
}

// ---------------- K4: binned radius-KNN top-16 + neighbor-weight reduction ----------------
__global__ void __launch_bounds__(256) knn_kernel(
    const float* __restrict__ fa, const float* __restrict__ fb,
    const float* __restrict__ knn_w, const float* __restrict__ knn_b)
{
    const int b = blockIdx.y, src = blockIdx.z;
    const int warpId = threadIdx.x >> 5, lane = threadIdx.x & 31;
    const int key = blockIdx.x * 8 + warpId;
    if (key >= NKEY) return;
    float2 kw = g_keyworld[b * NKEY + key];
    const float kx = kw.x, ky = kw.y;
    // radius^2 computed in double by python then compared in f32 by jnp
    const float r2 = (src == 0) ? 5.76f : 23.04f;
    const float cell = (src == 0) ? CELL0 : CELL1;
    const int dim = (src == 0) ? DIM0 : DIM1;
    int cx = min(dim - 1, max(0, (int)floorf((kx + 54.0f) / cell)));
    int cy = min(dim - 1, max(0, (int)floorf((ky + 54.0f) / cell)));

    unsigned long long lst[16];
    #pragma unroll
    for (int q = 0; q < 16; ++q) lst[q] = 0xFFFFFFFFFFFFFFFFull;

    const int* cstart = g_cellstart[src][b];
    const float2* sw = g_sortedWorld[src][b];
    const int* sidx = g_sortedIdx[src][b];

    for (int dy = -1; dy <= 1; ++dy) {
        int yy = cy + dy;
        if (yy < 0 || yy >= dim) continue;
        for (int dx = -1; dx <= 1; ++dx) {
            int xx = cx + dx;
            if (xx < 0 || xx >= dim) continue;
            int cid = yy * dim + xx;
            int s = cstart[cid], e = cstart[cid + 1];
            for (int i = s + lane; i < e; i += 32) {
                float2 p = sw[i];
                float ddx = kx - p.x;
                float ddy = ky - p.y;
                float d2 = __fadd_rn(__fmul_rn(ddx, ddx), __fmul_rn(ddy, ddy));
                if (d2 <= r2) {
                    unsigned long long kk =
                        ((unsigned long long)__float_as_uint(d2) << 32) |
                        (unsigned long long)(unsigned)sidx[i];
                    if (kk < lst[15]) {
                        unsigned long long cur = kk;
                        #pragma unroll
                        for (int q = 0; q < 16; ++q) {
                            unsigned long long mn = lst[q] < cur ? lst[q] : cur;
                            cur = lst[q] < cur ? cur : lst[q];
                            lst[q] = mn;
                        }
                    }
                }
            }
        }
    }

    // warp merge + immediate gather: extract the 16 globally-smallest keys
    const float* feat = ((src == 0) ? fa : fb) + (size_t)b * NS * C;
    float4 acc = make_float4(0.f, 0.f, 0.f, 0.f);
    int hp = 0;
    for (int r = 0; r < 16; ++r) {
        unsigned long long mine = (hp < 16) ? lst[hp] : 0xFFFFFFFFFFFFFFFFull;
        unsigned long long best = mine;
        #pragma unroll
        for (int o = 16; o; o >>= 1) {
            unsigned long long other = __shfl_xor_sync(0xffffffffu, best, o);
            best = other < best ? other : best;
        }
        if (best == 0xFFFFFFFFFFFFFFFFull) break;
        unsigned msk = __ballot_sync(0xffffffffu, mine == best);
        if (lane == __ffs((int)msk) - 1) hp++;
        unsigned idx = (unsigned)(best & 0xFFFFFFFFull);
        float4 v = *(const float4*)(feat + (size_t)idx * C + lane * 4);
        float w = knn_w[src * 16 + r];
        acc.x += w * v.x; acc.y += w * v.y; acc.z += w * v.z; acc.w += w * v.w;
    }
    float bb = knn_b[src];
    float* dst = (src == 0 ? g_mf0 : g_mf1) + (size_t)(b * NKEY + key) * C + lane * 4;
    dst[0] = acc.x + bb; dst[1] = acc.y + bb; dst[2] = acc.z + bb; dst[3] = acc.w + bb;
}

// ---------------- K5: kw MLP + softmax fusion + fuse MLP ----------------
__global__ void __launch_bounds__(256) fuse_kernel(
    const float* __restrict__ fusion_feat,
    const float* __restrict__ kw1, const float* __restrict__ kg1,
    const float* __restrict__ kb1, const float* __restrict__ kw2,
    const float* __restrict__ kb2,
    const float* __restrict__ fw1, const float* __restrict__ fg1,
    const float* __restrict__ fb1, const float* __restrict__ fw2,
    const float* __restrict__ fb2, float* __restrict__ outF)
{
    __shared__ float kf[8][128];
    __shared__ float h64[8][64];
    __shared__ float logit[8][3];
    __shared__ float sw[8][3];
    __shared__ float fused[8][256];
    __shared__ float h256[8][256];
    const int tid = threadIdx.x;
    const int g0 = blockIdx.x * 8;

    for (int t = tid; t < 8 * 128; t += 256) {
        int k = t >> 7, c = t & 127;
        int g = g0 + k;
        int b = g / NKEY;
        int ki = g_topk[g];
        kf[k][c] = fusion_feat[((size_t)b * NF + ki) * C + c];
    }
    __syncthreads();
    for (int t = tid; t < 512; t += 256) {
        int k = t >> 6, j = t & 63;
        float a = 0.f;
        for (int i = 0; i < 128; ++i) a += kf[k][i] * kw1[i * 64 + j];
        a = a * kg1[j] + kb1[j];
        h64[k][j] = a > 0.f ? a : 0.f;
    }
    __syncthreads();
    if (tid < 24) {
        int k = tid / 3, j = tid - k * 3;
        float a = 0.f;
        for (int i = 0; i < 64; ++i) a += h64[k][i] * kw2[i * 3 + j];
        logit[k][j] = a + kb2[j];
    }
    __syncthreads();
    if (tid < 8) {
        float l0 = logit[tid][0], l1 = logit[tid][1], l2 = logit[tid][2];
        float m = fmaxf(l0, fmaxf(l1, l2));
        float e0 = expf(l0 - m), e1 = expf(l1 - m), e2 = expf(l2 - m);
        float s = e0 + e1 + e2;
        sw[tid][0] = e0 / s; sw[tid][1] = e1 / s; sw[tid][2] = e2 / s;
    }
    __syncthreads();
    for (int t = tid; t < 1024; t += 256) {
        int k = t >> 7, c = t & 127;
        int g = g0 + k;
        float x = kf[k][c];
        float kv = sw[k][0] * x;
        float fs = kv * g_mf0[(size_t)g * C + c];
        kv = sw[k][1] * kv;
        fs += kv * g_mf1[(size_t)g * C + c];
        fused[k][c] = fs;
        fused[k][128 + c] = kv;
    }
    __syncthreads();
    {
        float acc[8];
        #pragma unroll
        for (int k = 0; k < 8; ++k) acc[k] = 0.f;
        for (int i = 0; i < 256; ++i) {
            float wv = fw1[i * 256 + tid];
            #pragma unroll
            for (int k = 0; k < 8; ++k) acc[k] += fused[k][i] * wv;
        }
        float gg = fg1[tid], bb = fb1[tid];
        #pragma unroll
        for (int k = 0; k < 8; ++k) {
            float h = acc[k] * gg + bb;
            h256[k][tid] = h > 0.f ? h : 0.f;
        }
    }
    __syncthreads();
    for (int t = tid; t < 1024; t += 256) {
        int k = t >> 7, c = t & 127;
        int g = g0 + k;
        float a = 0.f;
        for (int i = 0; i < 256; ++i) a += h256[k][i] * fw2[i * 128 + c];
        outF[OUT_OFF + (size_t)g * 128 + c] = a + fb2[c];
    }
}

// ---------------- launch ----------------
extern "C" void kernel_launch(void* const* d_in, const int* in_sizes, int n_in,
                              void* d_out, int out_size)
{
    const float* fusion_feat = (const float*)d_in[0];
    const float* src_feat_a  = (const float*)d_in[1];
    const float* src_feat_b  = (const float*)d_in[2];
    const float* heat_w1 = (const float*)d_in[3];
    const float* heat_g1 = (const float*)d_in[4];
    const float* heat_b1 = (const float*)d_in[5];
    const float* heat_w2 = (const float*)d_in[6];
    const float* heat_b2 = (const float*)d_in[7];
    const float* knn_w = (const float*)d_in[8];
    const float* knn_b = (const float*)d_in[9];
    const float* kw_w1 = (const float*)d_in[10];
    const float* kw_g1 = (const float*)d_in[11];
    const float* kw_b1 = (const float*)d_in[12];
    const float* kw_w2 = (const float*)d_in[13];
    const float* kw_b2 = (const float*)d_in[14];
    const float* fuse_w1 = (const float*)d_in[15];
    const float* fuse_g1 = (const float*)d_in[16];
    const float* fuse_b1 = (const float*)d_in[17];
    const float* fuse_w2 = (const float*)d_in[18];
    const float* fuse_b2 = (const float*)d_in[19];
    const int* fusion_coords = (const int*)d_in[20];
    const int* src_coords_a  = (const int*)d_in[21];
    const int* src_coords_b  = (const int*)d_in[22];
    float* outF = (float*)d_out;

    cudaFuncSetAttribute(heat_kernel, cudaFuncAttributeMaxDynamicSharedMemorySize, HEAT_SMEM);
    cudaFuncSetAttribute(topk_kernel, cudaFuncAttributeMaxDynamicSharedMemorySize, TOPK_SMEM);

    bin_zero_kernel<<<1, 1024>>>();
    bin_hist_kernel<<<(2 * B * NS + 255) / 256, 256>>>(src_coords_a, src_coords_b);
    bin_prefix_kernel<<<2 * B, 1024>>>();
    bin_scatter_kernel<<<(2 * B * NS + 255) / 256, 256>>>();
    heat_kernel<<<NROWS / 64, 128, HEAT_SMEM>>>(fusion_feat, heat_w1, heat_g1,
                                                heat_b1, heat_w2, heat_b2, outF);
    topk_kernel<<<B, 1024, TOPK_SMEM>>>(fusion_coords, outF);
    dim3 kg((NKEY + 7) / 8, B, 2);
    knn_kernel<<<kg, 256>>>(src_feat_a, src_feat_b, knn_w, knn_b);
    fuse_kernel<<<(B * NKEY) / 8, 256>>>(fusion_feat, kw_w1, kw_g1, kw_b1, kw_w2,
                                         kw_b2, fuse_w1, fuse_g1, fuse_b1,
                                         fuse_w2, fuse_b2, outF);
}

// round 5
// speedup vs baseline: 1.7426x; 1.1459x over previous
#include <cuda_runtime.h>
#include <math.h>

#define B 2
#define NF 20000
#define NS 30000
#define C 128
#define NKEY 500
#define NROWS (B*NF)

// output layout (flattened, float32, in reference return order)
#define OUT_OFF  0        // (1000,128)
#define KVI_OFF  128000   // (1000,3)
#define HEAT_OFF 131000   // (40000,)
#define S10_OFF  171000   // (40000,10)
#define KC_OFF   571000   // (1000,)

// spatial binning params (cell > radius with wide margin -> 3x3 ring suffices)
#define DIM0 36
#define CELL0 3.0f
#define DIM1 22
#define CELL1 5.0f
#define NCELLMAX (DIM0*DIM0)   // 1296
#define CAP 192                // fixed per-cell capacity (avg 23 / 62; huge margin)

// ---------------- scratch (device globals; no allocs allowed) ----------------
__device__ float g_sig[NROWS];
__device__ int   g_cls[NROWS];
__device__ int   g_topk[B*NKEY];
__device__ float2 g_keyworld[B*NKEY];
__device__ float g_mf0[B*NKEY*C];
__device__ float g_mf1[B*NKEY*C];
__device__ int    g_cellcnt[2][B][NCELLMAX];
__device__ float4 g_cellpts[2][B][NCELLMAX*CAP];   // {wx, wy, idx-bits, 0}

__device__ __forceinline__ float worldc(int c, float stride) {
    // ((c + 0.5) * stride) * 0.075 + (-54), each op fp32-rounded, no contraction
    float t = __fadd_rn((float)c, 0.5f);
    t = __fmul_rn(t, stride);
    t = __fmul_rn(t, 0.075f);
    return __fadd_rn(t, -54.0f);
}

// ---------------- bins: zero + single-pass build ----------------
__global__ void bin_zero_kernel() {
    int i = blockIdx.x * 1024 + threadIdx.x;
    if (i < 2 * B * NCELLMAX) ((int*)g_cellcnt)[i] = 0;
}

__global__ void bin_build_kernel(const int* __restrict__ ca, const int* __restrict__ cb) {
    int id = blockIdx.x * 256 + threadIdx.x;
    if (id >= 2 * B * NS) return;
    int src = id / (B * NS);
    int rem = id - src * (B * NS);
    int b = rem / NS, i = rem - b * NS;
    int2 cc = ((const int2*)(src == 0 ? ca : cb))[b * NS + i];
    float stride = (src == 0) ? 4.0f : 8.0f;
    float wx = worldc(cc.x, stride), wy = worldc(cc.y, stride);
    float cell = (src == 0) ? CELL0 : CELL1;
    int dim = (src == 0) ? DIM0 : DIM1;
    int cx = min(dim - 1, max(0, (int)floorf((wx + 54.0f) / cell)));
    int cy = min(dim - 1, max(0, (int)floorf((wy + 54.0f) / cell)));
    int cid = cy * dim + cx;
    int pos = atomicAdd(&g_cellcnt[src][b][cid], 1);
    if (pos < CAP)
        g_cellpts[src][b][cid * CAP + pos] =
            make_float4(wx, wy, __uint_as_float((unsigned)i), 0.f);
}

// ---------------- K1: heat MLP (40000 x 128 -> 128 relu -> 10) ----------------
// X tile in shared; W1 streamed from L2 (hot, 64KB) -> high occupancy.
#define SXS 132   // padded row stride for shared X/H
#define HEAT_SMEM ((64*SXS + 128*12 + 64*10) * 4)

__global__ void __launch_bounds__(256) heat_kernel(
    const float* __restrict__ X, const float* __restrict__ W1,
    const float* __restrict__ G1, const float* __restrict__ B1,
    const float* __restrict__ W2, const float* __restrict__ B2v,
    float* __restrict__ outF)
{
    extern __shared__ float sm[];
    float* sX  = sm;                     // 64 * SXS
    float* sW2 = sm + 64 * SXS;          // 128 * 12 (padded, cols>=10 zero)
    float* sS  = sW2 + 128 * 12;         // 64 * 10
    const int tid = threadIdx.x;
    const int rowbase = blockIdx.x * 64;

    // load X tile (64x128) into padded shared
    {
        const float4* s = (const float4*)(X + (size_t)rowbase * C);
        #pragma unroll
        for (int t = 0; t < 8; ++t) {
            int idx = tid + t * 256;         // 0..2047 float4s
            int row = idx >> 5, c4 = idx & 31;
            *(float4*)(sX + row * SXS + c4 * 4) = s[idx];
        }
    }
    // load W2 padded to 12 cols
    for (int t = tid; t < 128 * 12; t += 256) {
        int i = t / 12, c = t - i * 12;
        sW2[t] = (c < 10) ? W2[i * 10 + c] : 0.f;
    }
    __syncthreads();

    // 16 thread-rows x 16 thread-cols; 4x8 micro-tile per thread
    const int ty = tid >> 4, tx = tid & 15;
    const int r0 = ty * 4, c0 = tx * 8;
    float acc[4][8];
    #pragma unroll
    for (int i = 0; i < 4; ++i)
        #pragma unroll
        for (int j = 0; j < 8; ++j) acc[i][j] = 0.f;

    #pragma unroll 2
    for (int k = 0; k < 128; k += 4) {
        float4 w[8];
        #pragma unroll
        for (int kk = 0; kk < 4; ++kk) {
            w[2*kk]   = __ldg((const float4*)(W1 + (k + kk) * 128 + c0));
            w[2*kk+1] = __ldg((const float4*)(W1 + (k + kk) * 128 + c0 + 4));
        }
        float4 xr[4];
        #pragma unroll
        for (int i = 0; i < 4; ++i)
            xr[i] = *(const float4*)&sX[(r0 + i) * SXS + k];
        #pragma unroll
        for (int kk = 0; kk < 4; ++kk) {
            #pragma unroll
            for (int i = 0; i < 4; ++i) {
                float x = (kk == 0) ? xr[i].x : (kk == 1) ? xr[i].y
                        : (kk == 2) ? xr[i].z : xr[i].w;
                acc[i][0] += x * w[2*kk].x;   acc[i][1] += x * w[2*kk].y;
                acc[i][2] += x * w[2*kk].z;   acc[i][3] += x * w[2*kk].w;
                acc[i][4] += x * w[2*kk+1].x; acc[i][5] += x * w[2*kk+1].y;
                acc[i][6] += x * w[2*kk+1].z; acc[i][7] += x * w[2*kk+1].w;
            }
        }
    }
    float4 ga = *(const float4*)&G1[c0], gb = *(const float4*)&G1[c0 + 4];
    float4 ba = *(const float4*)&B1[c0], bb = *(const float4*)&B1[c0 + 4];
    float gv[8] = {ga.x, ga.y, ga.z, ga.w, gb.x, gb.y, gb.z, gb.w};
    float bv[8] = {ba.x, ba.y, ba.z, ba.w, bb.x, bb.y, bb.z, bb.w};
    __syncthreads();  // all reads of sX done; safe to overwrite with H
    #pragma unroll
    for (int i = 0; i < 4; ++i)
        #pragma unroll
        for (int j = 0; j < 8; ++j) {
            float h = acc[i][j] * gv[j] + bv[j];
            sX[(r0 + i) * SXS + c0 + j] = h > 0.f ? h : 0.f;
        }
    __syncthreads();

    // stage 2: scores10 = H @ W2 + b2  (2 threads per row, 5 cols each)
    if (tid < 128) {
        const int r = tid >> 1, hhalf = tid & 1;
        const int cc0 = hhalf * 5;
        float a[5] = {0.f, 0.f, 0.f, 0.f, 0.f};
        for (int i = 0; i < 128; ++i) {
            float hv = sX[r * SXS + i];
            #pragma unroll
            for (int q = 0; q < 5; ++q) a[q] += hv * sW2[i * 12 + cc0 + q];
        }
        #pragma unroll
        for (int q = 0; q < 5; ++q) {
            int c = cc0 + q;
            float v = a[q] + B2v[c];
            outF[S10_OFF + (size_t)(rowbase + r) * 10 + c] = v;
            sS[r * 10 + c] = v;
        }
    }
    __syncthreads();
    if (tid < 64) {
        int r = tid, row = rowbase + r;
        float m = -INFINITY; int a = 0;
        #pragma unroll
        for (int c = 0; c < 10; ++c) {
            float v = sS[r * 10 + c];
            if (v > m) { m = v; a = c; }   // first max wins (jnp.argmax)
        }
        outF[HEAT_OFF + row] = m;
        g_sig[row] = 1.f / (1.f + expf(-m));
        g_cls[row] = a;
    }
}

// ---------------- K2: per-batch top-500 (jax.lax.top_k semantics) ----------------
// histogram-accelerated threshold search + exact tie handling via packed keys
#define TOPK_SMEM (NF*4 + 1024*8 + 2048*8)

__global__ void __launch_bounds__(1024) topk_kernel(
    const int* __restrict__ fusion_coords, float* __restrict__ outF)
{
    extern __shared__ unsigned char dsm[];
    unsigned* sbits = (unsigned*)dsm;                                      // NF
    unsigned long long* cand  = (unsigned long long*)(dsm + NF * 4);       // 1024
    unsigned long long* blist = (unsigned long long*)(dsm + NF * 4 + 8192);// 2048
    __shared__ int hist[1024];
    __shared__ int scum[1024];
    __shared__ int warpsum[32];
    __shared__ int s_bin, s_above, s_m, s_cnt, s_n;
    __shared__ unsigned s_lo, s_hi;
    const int tid = threadIdx.x;
    const int lane = tid & 31, wid = tid >> 5;
    const int b = blockIdx.x;

    hist[tid] = 0;
    __syncthreads();
    for (int i = tid; i < NF; i += 1024) {
        unsigned v = __float_as_uint(g_sig[b * NF + i]);
        sbits[i] = v;
        atomicAdd(&hist[v >> 20], 1);   // sigmoid in (0,1] -> bits <= 0x3F800000 -> bin <= 1016
    }
    __syncthreads();
    // suffix-cum via reverse inclusive prefix: scum[t] = sum over bins >= 1023-t
    {
        int v = hist[1023 - tid];
        #pragma unroll
        for (int o = 1; o < 32; o <<= 1) {
            int t = __shfl_up_sync(0xffffffffu, v, o);
            if (lane >= o) v += t;
        }
        if (lane == 31) warpsum[wid] = v;
        __syncthreads();
        if (wid == 0) {
            int w = warpsum[lane];
            #pragma unroll
            for (int o = 1; o < 32; o <<= 1) {
                int t = __shfl_up_sync(0xffffffffu, w, o);
                if (lane >= o) w += t;
            }
            warpsum[lane] = w;
        }
        __syncthreads();
        scum[tid] = v + ((wid > 0) ? warpsum[wid - 1] : 0);
    }
    if (tid == 0) s_m = 0;
    __syncthreads();
    {   // threshold bin: largest j with cum[j] >= NKEY (cum[j] = scum[1023-j])
        int c1 = scum[1023 - tid];
        int c2 = (tid == 1023) ? 0 : scum[1022 - tid];
        if (c1 >= NKEY && c2 < NKEY) { s_bin = tid; s_above = c2; }
    }
    __syncthreads();
    const int bin = s_bin;
    const int kprime = NKEY - s_above;
    // collect threshold-bin elements
    for (int i = tid; i < NF; i += 1024) {
        unsigned v = sbits[i];
        if ((int)(v >> 20) == bin) {
            int p = atomicAdd(&s_m, 1);
            if (p < 2048)
                blist[p] = ((unsigned long long)v << 32) |
                           (unsigned long long)(0xFFFFFFFFu - (unsigned)i);
        }
    }
    __syncthreads();
    const int m = s_m;
    const bool small = (m <= 2048);
    if (tid == 0) { s_lo = (unsigned)bin << 20; s_hi = ((unsigned)bin + 1u) << 20; }
    __syncthreads();
    // 20-bit refinement: max t with count(>= t) >= target
    for (int it = 0; it < 20; ++it) {
        unsigned lo = s_lo, hi = s_hi;
        unsigned mid = lo + ((hi - lo) >> 1);
        if (tid == 0) s_cnt = 0;
        __syncthreads();
        int c = 0;
        if (small) {
            if (tid < m)        c += ((unsigned)(blist[tid] >> 32) >= mid);
            if (tid + 1024 < m) c += ((unsigned)(blist[tid + 1024] >> 32) >= mid);
        } else {
            for (int i = tid; i < NF; i += 1024) c += (sbits[i] >= mid) ? 1 : 0;
        }
        #pragma unroll
        for (int o = 16; o; o >>= 1) c += __shfl_xor_sync(0xffffffffu, c, o);
        if (lane == 0 && c) atomicAdd(&s_cnt, c);
        __syncthreads();
        int target = small ? kprime : NKEY;
        if (tid == 0) { if (s_cnt >= target) s_lo = mid; else s_hi = mid; }
        __syncthreads();
    }
    unsigned thr = s_lo;
    if (tid == 0) s_n = 0;
    __syncthreads();
    for (int i = tid; i < NF; i += 1024) {
        unsigned v = sbits[i];
        if (v >= thr) {
            int p = atomicAdd(&s_n, 1);
            if (p < 1024)
                cand[p] = ((unsigned long long)v << 32) |
                          (unsigned long long)(0xFFFFFFFFu - (unsigned)i);
        }
    }
    __syncthreads();
    int n = s_n; if (n > 1024) n = 1024;
    if (tid >= n) cand[tid] = 0ull;
    __syncthreads();
    // bitonic sort ascending, 1024 elems
    for (int k = 2; k <= 1024; k <<= 1) {
        for (int j = k >> 1; j > 0; j >>= 1) {
            int ixj = tid ^ j;
            if (ixj > tid) {
                unsigned long long a = cand[tid], d = cand[ixj];
                bool up = ((tid & k) == 0);
                if ((a > d) == up) { cand[tid] = d; cand[ixj] = a; }
            }
            __syncthreads();
        }
    }
    if (tid < NKEY) {
        unsigned long long key = cand[1023 - tid];
        unsigned idx = 0xFFFFFFFFu - (unsigned)(key & 0xFFFFFFFFull);
        g_topk[b * NKEY + tid] = (int)idx;
        int2 cc = ((const int2*)fusion_coords)[b * NF + (int)idx];
        int o = (b * NKEY + tid) * 3;
        outF[KVI_OFF + o + 0] = (float)b;
        outF[KVI_OFF + o + 1] = (float)cc.x;
        outF[KVI_OFF + o + 2] = (float)cc.y;
        g_keyworld[b * NKEY + tid] = make_float2(worldc(cc.x, 8.0f), worldc(cc.y, 8.0f));
        outF[KC_OFF + b * NKEY + tid] = (float)g_cls[b * NF + (int)idx];
    }
}

// ---------------- K4: binned radius-KNN top-16 + neighbor-weight reduction ----------------
__global__ void __launch_bounds__(256) knn_kernel(
    const float* __restrict__ fa, const float* __restrict__ fb,
    const float* __restrict__ knn_w, const float* __restrict__ knn_b)
{
    const int b = blockIdx.y, src = blockIdx.z;
    const int warpId = threadIdx.x >> 5, lane = threadIdx.x & 31;
    const int key = blockIdx.x * 8 + warpId;
    if (key >= NKEY) return;
    float2 kw = g_keyworld[b * NKEY + key];
    const float kx = kw.x, ky = kw.y;
    // radius^2 computed in double by python then compared in f32 by jnp
    const float r2 = (src == 0) ? 5.76f : 23.04f;
    const float cell = (src == 0) ? CELL0 : CELL1;
    const int dim = (src == 0) ? DIM0 : DIM1;
    int cx = min(dim - 1, max(0, (int)floorf((kx + 54.0f) / cell)));
    int cy = min(dim - 1, max(0, (int)floorf((ky + 54.0f) / cell)));

    unsigned long long lst[16];
    #pragma unroll
    for (int q = 0; q < 16; ++q) lst[q] = 0xFFFFFFFFFFFFFFFFull;

    const int* ccnt = g_cellcnt[src][b];
    const float4* cpts = g_cellpts[src][b];

    for (int dy = -1; dy <= 1; ++dy) {
        int yy = cy + dy;
        if (yy < 0 || yy >= dim) continue;
        for (int dx = -1; dx <= 1; ++dx) {
            int xx = cx + dx;
            if (xx < 0 || xx >= dim) continue;
            int cid = yy * dim + xx;
            int e = min(ccnt[cid], CAP);
            const float4* cp = cpts + cid * CAP;
            for (int i = lane; i < e; i += 32) {
                float4 p = cp[i];
                float ddx = kx - p.x;
                float ddy = ky - p.y;
                float d2 = __fadd_rn(__fmul_rn(ddx, ddx), __fmul_rn(ddy, ddy));
                if (d2 <= r2) {
                    unsigned long long kk =
                        ((unsigned long long)__float_as_uint(d2) << 32) |
                        (unsigned long long)__float_as_uint(p.z);
                    if (kk < lst[15]) {
                        unsigned long long cur = kk;
                        #pragma unroll
                        for (int q = 0; q < 16; ++q) {
                            unsigned long long mn = lst[q] < cur ? lst[q] : cur;
                            cur = lst[q] < cur ? cur : lst[q];
                            lst[q] = mn;
                        }
                    }
                }
            }
        }
    }

    // warp merge + immediate gather: extract the 16 globally-smallest keys
    const float* feat = ((src == 0) ? fa : fb) + (size_t)b * NS * C;
    float4 acc = make_float4(0.f, 0.f, 0.f, 0.f);
    int hp = 0;
    for (int r = 0; r < 16; ++r) {
        unsigned long long mine = (hp < 16) ? lst[hp] : 0xFFFFFFFFFFFFFFFFull;
        unsigned long long best = mine;
        #pragma unroll
        for (int o = 16; o; o >>= 1) {
            unsigned long long other = __shfl_xor_sync(0xffffffffu, best, o);
            best = other < best ? other : best;
        }
        if (best == 0xFFFFFFFFFFFFFFFFull) break;
        unsigned msk = __ballot_sync(0xffffffffu, mine == best);
        if (lane == __ffs((int)msk) - 1) hp++;
        unsigned idx = (unsigned)(best & 0xFFFFFFFFull);
        float4 v = *(const float4*)(feat + (size_t)idx * C + lane * 4);
        float w = knn_w[src * 16 + r];
        acc.x += w * v.x; acc.y += w * v.y; acc.z += w * v.z; acc.w += w * v.w;
    }
    float bb = knn_b[src];
    float* dst = (src == 0 ? g_mf0 : g_mf1) + (size_t)(b * NKEY + key) * C + lane * 4;
    dst[0] = acc.x + bb; dst[1] = acc.y + bb; dst[2] = acc.z + bb; dst[3] = acc.w + bb;
}

// ---------------- K5: kw MLP + softmax fusion + fuse MLP ----------------
__global__ void __launch_bounds__(256) fuse_kernel(
    const float* __restrict__ fusion_feat,
    const float* __restrict__ kw1, const float* __restrict__ kg1,
    const float* __restrict__ kb1, const float* __restrict__ kw2,
    const float* __restrict__ kb2,
    const float* __restrict__ fw1, const float* __restrict__ fg1,
    const float* __restrict__ fb1, const float* __restrict__ fw2,
    const float* __restrict__ fb2, float* __restrict__ outF)
{
    __shared__ float kf[8][128];
    __shared__ float h64[8][64];
    __shared__ float logit[8][3];
    __shared__ float sw[8][3];
    __shared__ float fused[8][256];
    __shared__ float h256[8][256];
    const int tid = threadIdx.x;
    const int g0 = blockIdx.x * 8;

    for (int t = tid; t < 8 * 128; t += 256) {
        int k = t >> 7, c = t & 127;
        int g = g0 + k;
        int b = g / NKEY;
        int ki = g_topk[g];
        kf[k][c] = fusion_feat[((size_t)b * NF + ki) * C + c];
    }
    __syncthreads();
    for (int t = tid; t < 512; t += 256) {
        int k = t >> 6, j = t & 63;
        float a = 0.f;
        for (int i = 0; i < 128; ++i) a += kf[k][i] * kw1[i * 64 + j];
        a = a * kg1[j] + kb1[j];
        h64[k][j] = a > 0.f ? a : 0.f;
    }
    __syncthreads();
    if (tid < 24) {
        int k = tid / 3, j = tid - k * 3;
        float a = 0.f;
        for (int i = 0; i < 64; ++i) a += h64[k][i] * kw2[i * 3 + j];
        logit[k][j] = a + kb2[j];
    }
    __syncthreads();
    if (tid < 8) {
        float l0 = logit[tid][0], l1 = logit[tid][1], l2 = logit[tid][2];
        float m = fmaxf(l0, fmaxf(l1, l2));
        float e0 = expf(l0 - m), e1 = expf(l1 - m), e2 = expf(l2 - m);
        float s = e0 + e1 + e2;
        sw[tid][0] = e0 / s; sw[tid][1] = e1 / s; sw[tid][2] = e2 / s;
    }
    __syncthreads();
    for (int t = tid; t < 1024; t += 256) {
        int k = t >> 7, c = t & 127;
        int g = g0 + k;
        float x = kf[k][c];
        float kv = sw[k][0] * x;
        float fs = kv * g_mf0[(size_t)g * C + c];
        kv = sw[k][1] * kv;
        fs += kv * g_mf1[(size_t)g * C + c];
        fused[k][c] = fs;
        fused[k][128 + c] = kv;
    }
    __syncthreads();
    {
        float acc[8];
        #pragma unroll
        for (int k = 0; k < 8; ++k) acc[k] = 0.f;
        for (int i = 0; i < 256; ++i) {
            float wv = fw1[i * 256 + tid];
            #pragma unroll
            for (int k = 0; k < 8; ++k) acc[k] += fused[k][i] * wv;
        }
        float gg = fg1[tid], bb = fb1[tid];
        #pragma unroll
        for (int k = 0; k < 8; ++k) {
            float h = acc[k] * gg + bb;
            h256[k][tid] = h > 0.f ? h : 0.f;
        }
    }
    __syncthreads();
    for (int t = tid; t < 1024; t += 256) {
        int k = t >> 7, c = t & 127;
        int g = g0 + k;
        float a = 0.f;
        for (int i = 0; i < 256; ++i) a += h256[k][i] * fw2[i * 128 + c];
        outF[OUT_OFF + (size_t)g * 128 + c] = a + fb2[c];
    }
}

// ---------------- launch ----------------
extern "C" void kernel_launch(void* const* d_in, const int* in_sizes, int n_in,
                              void* d_out, int out_size)
{
    const float* fusion_feat = (const float*)d_in[0];
    const float* src_feat_a  = (const float*)d_in[1];
    const float* src_feat_b  = (const float*)d_in[2];
    const float* heat_w1 = (const float*)d_in[3];
    const float* heat_g1 = (const float*)d_in[4];
    const float* heat_b1 = (const float*)d_in[5];
    const float* heat_w2 = (const float*)d_in[6];
    const float* heat_b2 = (const float*)d_in[7];
    const float* knn_w = (const float*)d_in[8];
    const float* knn_b = (const float*)d_in[9];
    const float* kw_w1 = (const float*)d_in[10];
    const float* kw_g1 = (const float*)d_in[11];
    const float* kw_b1 = (const float*)d_in[12];
    const float* kw_w2 = (const float*)d_in[13];
    const float* kw_b2 = (const float*)d_in[14];
    const float* fuse_w1 = (const float*)d_in[15];
    const float* fuse_g1 = (const float*)d_in[16];
    const float* fuse_b1 = (const float*)d_in[17];
    const float* fuse_w2 = (const float*)d_in[18];
    const float* fuse_b2 = (const float*)d_in[19];
    const int* fusion_coords = (const int*)d_in[20];
    const int* src_coords_a  = (const int*)d_in[21];
    const int* src_coords_b  = (const int*)d_in[22];
    float* outF = (float*)d_out;

    cudaFuncSetAttribute(heat_kernel, cudaFuncAttributeMaxDynamicSharedMemorySize, HEAT_SMEM);
    cudaFuncSetAttribute(topk_kernel, cudaFuncAttributeMaxDynamicSharedMemorySize, TOPK_SMEM);

    bin_zero_kernel<<<(2 * B * NCELLMAX + 1023) / 1024, 1024>>>();
    bin_build_kernel<<<(2 * B * NS + 255) / 256, 256>>>(src_coords_a, src_coords_b);
    heat_kernel<<<NROWS / 64, 256, HEAT_SMEM>>>(fusion_feat, heat_w1, heat_g1,
                                                heat_b1, heat_w2, heat_b2, outF);
    topk_kernel<<<B, 1024, TOPK_SMEM>>>(fusion_coords, outF);
    dim3 kg((NKEY + 7) / 8, B, 2);
    knn_kernel<<<kg, 256>>>(src_feat_a, src_feat_b, knn_w, knn_b);
    fuse_kernel<<<(B * NKEY) / 8, 256>>>(fusion_feat, kw_w1, kw_g1, kw_b1, kw_w2,
                                         kw_b2, fuse_w1, fuse_g1, fuse_b1,
                                         fuse_w2, fuse_b2, outF);
}